// round 1
// baseline (speedup 1.0000x reference)
#include <cuda_runtime.h>
#include <math.h>

// Problem constants
#define NEXP 8
#define TOPK 2
#define DH   1024
#define FH   4096
#define NTOK 4096   // B*S = 4*1024
#define NSLOT (NTOK * TOPK)   // 8192

// ---------------- scratch (static __device__ — no allocations) -------------
__device__ float g_H[(size_t)NSLOT * FH];   // 134 MB: gelu(x@fc_w+b) per slot
__device__ float g_O[(size_t)NSLOT * DH];   // 33.5 MB: weighted expert outputs
__device__ int   g_count[NEXP];
__device__ int   g_cursor[NEXP];
__device__ int   g_off[NEXP + 1];
__device__ int   g_eid[NSLOT];    // per (token,k): expert id
__device__ float g_wk[NSLOT];     // per (token,k): routing weight
__device__ int   g_tok[NSLOT];    // per slot: token index
__device__ float g_wt[NSLOT];     // per slot: routing weight
__device__ int   g_slot[NSLOT];   // per (token,k): slot index

// ---------------- helpers ---------------------------------------------------
__device__ __forceinline__ float gelu_new(float v) {
    const float c = 0.7978845608028654f;   // sqrt(2/pi)
    float u = c * (v + 0.044715f * v * v * v);
    return 0.5f * v * (1.0f + tanhf(u));
}

// ---------------- kernel 0: reset counters ----------------------------------
__global__ void init_kernel() {
    int i = threadIdx.x;
    if (i < NEXP) { g_count[i] = 0; g_cursor[i] = 0; }
}

// ---------------- kernel 1: router (logits, softmax top-2, weights) ---------
__global__ void router_kernel(const float* __restrict__ x,
                              const float* __restrict__ gate_w,
                              float* __restrict__ out_logits) {
    int warp = (blockIdx.x * blockDim.x + threadIdx.x) >> 5;
    int lane = threadIdx.x & 31;
    if (warp >= NTOK) return;
    const float* xp = x + (size_t)warp * DH;

    float acc[NEXP];
#pragma unroll
    for (int e = 0; e < NEXP; e++) acc[e] = 0.0f;

    for (int d = lane; d < DH; d += 32) {
        float xv = xp[d];
        const float* gw = gate_w + d * NEXP;
#pragma unroll
        for (int e = 0; e < NEXP; e++) acc[e] += xv * gw[e];
    }
#pragma unroll
    for (int e = 0; e < NEXP; e++) {
#pragma unroll
        for (int o = 16; o > 0; o >>= 1)
            acc[e] += __shfl_xor_sync(0xffffffffu, acc[e], o);
    }

    if (lane == 0) {
        if (out_logits) {
#pragma unroll
            for (int e = 0; e < NEXP; e++) out_logits[warp * NEXP + e] = acc[e];
        }
        // top-2 on logits (== top-2 on softmax probs), ties -> lowest index
        int e0 = 0;
#pragma unroll
        for (int e = 1; e < NEXP; e++) if (acc[e] > acc[e0]) e0 = e;
        int e1 = (e0 == 0) ? 1 : 0;
#pragma unroll
        for (int e = 0; e < NEXP; e++)
            if (e != e0 && acc[e] > acc[e1]) e1 = e;
        // normalized top-2 weights: softmax denominator cancels
        float dlt = expf(acc[e1] - acc[e0]);   // <= 1
        float w0 = 1.0f / (1.0f + dlt);
        float w1 = dlt / (1.0f + dlt);

        g_eid[warp * 2 + 0] = e0;  g_eid[warp * 2 + 1] = e1;
        g_wk [warp * 2 + 0] = w0;  g_wk [warp * 2 + 1] = w1;
        atomicAdd(&g_count[e0], 1);
        atomicAdd(&g_count[e1], 1);
    }
}

// ---------------- kernel 2: exclusive scan over 8 experts -------------------
__global__ void scan_kernel() {
    if (threadIdx.x == 0) {
        int acc = 0;
        g_off[0] = 0;
#pragma unroll
        for (int e = 0; e < NEXP; e++) { acc += g_count[e]; g_off[e + 1] = acc; }
    }
}

// ---------------- kernel 3: scatter tokens into per-expert lists ------------
__global__ void scatter_kernel() {
    int t = blockIdx.x * blockDim.x + threadIdx.x;
    if (t >= NTOK) return;
#pragma unroll
    for (int k = 0; k < TOPK; k++) {
        int e = g_eid[t * 2 + k];
        int pos = g_off[e] + atomicAdd(&g_cursor[e], 1);
        g_tok[pos] = t;
        g_wt[pos]  = g_wk[t * 2 + k];
        g_slot[t * 2 + k] = pos;
    }
}

// ---------------- tiled GEMM params ------------------------------------------
#define TM 64
#define TN 64
#define TK 16

// H[slot, n] = gelu( x[tok, :] @ fc_w[e][:, n] + fc_b[e][n] )
__global__ __launch_bounds__(256)
void gemm1_kernel(const float* __restrict__ x,
                  const float* __restrict__ fc_w,
                  const float* __restrict__ fc_b) {
    int e    = blockIdx.z;
    int row0 = g_off[e];
    int rows = g_off[e + 1] - row0;
    int m0   = blockIdx.y * TM;
    if (m0 >= rows) return;
    int n0   = blockIdx.x * TN;
    const float* B = fc_w + (size_t)e * DH * FH;

    __shared__ float As[TM][TK];
    __shared__ float Bs[TK][TN];

    int tid = threadIdx.x;
    int tx = tid & 15, ty = tid >> 4;

    // A load mapping: thread -> (row lm, 4 k-elems at lk)
    int lm = tid >> 2;
    int lk = (tid & 3) * 4;
    int arow = m0 + lm;
    const float* aptr = (arow < rows) ? (x + (size_t)g_tok[row0 + arow] * DH) : nullptr;

    // B load mapping: thread -> (k row kb, 4 n-elems at nb)
    int kb = tid >> 4;
    int nb = (tid & 15) * 4;

    float acc[4][4];
#pragma unroll
    for (int i = 0; i < 4; i++)
#pragma unroll
        for (int j = 0; j < 4; j++) acc[i][j] = 0.0f;

    for (int kt = 0; kt < DH; kt += TK) {
        float4 av = make_float4(0.f, 0.f, 0.f, 0.f);
        if (aptr) av = *(const float4*)(aptr + kt + lk);
        *(float4*)&As[lm][lk] = av;
        *(float4*)&Bs[kb][nb] =
            *(const float4*)(B + (size_t)(kt + kb) * FH + n0 + nb);
        __syncthreads();
#pragma unroll
        for (int k = 0; k < TK; k++) {
            float a0 = As[ty * 4 + 0][k];
            float a1 = As[ty * 4 + 1][k];
            float a2 = As[ty * 4 + 2][k];
            float a3 = As[ty * 4 + 3][k];
            float4 b = *(float4*)&Bs[k][tx * 4];
            acc[0][0] += a0 * b.x; acc[0][1] += a0 * b.y; acc[0][2] += a0 * b.z; acc[0][3] += a0 * b.w;
            acc[1][0] += a1 * b.x; acc[1][1] += a1 * b.y; acc[1][2] += a1 * b.z; acc[1][3] += a1 * b.w;
            acc[2][0] += a2 * b.x; acc[2][1] += a2 * b.y; acc[2][2] += a2 * b.z; acc[2][3] += a2 * b.w;
            acc[3][0] += a3 * b.x; acc[3][1] += a3 * b.y; acc[3][2] += a3 * b.z; acc[3][3] += a3 * b.w;
        }
        __syncthreads();
    }

    const float* bias = fc_b + (size_t)e * FH + n0 + tx * 4;
#pragma unroll
    for (int i = 0; i < 4; i++) {
        int r = m0 + ty * 4 + i;
        if (r < rows) {
            float* hp = g_H + (size_t)(row0 + r) * FH + n0 + tx * 4;
#pragma unroll
            for (int j = 0; j < 4; j++)
                hp[j] = gelu_new(acc[i][j] + bias[j]);
        }
    }
}

// O[slot, n] = wt[slot] * ( H[slot, :] @ proj_w[e][:, n] + proj_b[e][n] )
__global__ __launch_bounds__(256)
void gemm2_kernel(const float* __restrict__ proj_w,
                  const float* __restrict__ proj_b) {
    int e    = blockIdx.z;
    int row0 = g_off[e];
    int rows = g_off[e + 1] - row0;
    int m0   = blockIdx.y * TM;
    if (m0 >= rows) return;
    int n0   = blockIdx.x * TN;
    const float* B = proj_w + (size_t)e * FH * DH;

    __shared__ float As[TM][TK];
    __shared__ float Bs[TK][TN];

    int tid = threadIdx.x;
    int tx = tid & 15, ty = tid >> 4;

    int lm = tid >> 2;
    int lk = (tid & 3) * 4;
    int arow = m0 + lm;
    const float* aptr = (arow < rows) ? (g_H + (size_t)(row0 + arow) * FH) : nullptr;

    int kb = tid >> 4;
    int nb = (tid & 15) * 4;

    float acc[4][4];
#pragma unroll
    for (int i = 0; i < 4; i++)
#pragma unroll
        for (int j = 0; j < 4; j++) acc[i][j] = 0.0f;

    for (int kt = 0; kt < FH; kt += TK) {
        float4 av = make_float4(0.f, 0.f, 0.f, 0.f);
        if (aptr) av = *(const float4*)(aptr + kt + lk);
        *(float4*)&As[lm][lk] = av;
        *(float4*)&Bs[kb][nb] =
            *(const float4*)(B + (size_t)(kt + kb) * DH + n0 + nb);
        __syncthreads();
#pragma unroll
        for (int k = 0; k < TK; k++) {
            float a0 = As[ty * 4 + 0][k];
            float a1 = As[ty * 4 + 1][k];
            float a2 = As[ty * 4 + 2][k];
            float a3 = As[ty * 4 + 3][k];
            float4 b = *(float4*)&Bs[k][tx * 4];
            acc[0][0] += a0 * b.x; acc[0][1] += a0 * b.y; acc[0][2] += a0 * b.z; acc[0][3] += a0 * b.w;
            acc[1][0] += a1 * b.x; acc[1][1] += a1 * b.y; acc[1][2] += a1 * b.z; acc[1][3] += a1 * b.w;
            acc[2][0] += a2 * b.x; acc[2][1] += a2 * b.y; acc[2][2] += a2 * b.z; acc[2][3] += a2 * b.w;
            acc[3][0] += a3 * b.x; acc[3][1] += a3 * b.y; acc[3][2] += a3 * b.z; acc[3][3] += a3 * b.w;
        }
        __syncthreads();
    }

    const float* bias = proj_b + (size_t)e * DH + n0 + tx * 4;
#pragma unroll
    for (int i = 0; i < 4; i++) {
        int r = m0 + ty * 4 + i;
        if (r < rows) {
            float w = g_wt[row0 + r];
            float* op = g_O + (size_t)(row0 + r) * DH + n0 + tx * 4;
#pragma unroll
            for (int j = 0; j < 4; j++)
                op[j] = w * (acc[i][j] + bias[j]);
        }
    }
}

// ---------------- kernel 6: deterministic per-token combine ------------------
__global__ void combine_kernel(float* __restrict__ out) {
    int idx = blockIdx.x * blockDim.x + threadIdx.x;   // over NTOK * DH / 4
    const int DQ = DH / 4;
    if (idx >= NTOK * DQ) return;
    int t  = idx / DQ;
    int dq = idx - t * DQ;
    int s0 = g_slot[t * 2 + 0];
    int s1 = g_slot[t * 2 + 1];
    const float4* o0 = (const float4*)(g_O + (size_t)s0 * DH) + dq;
    const float4* o1 = (const float4*)(g_O + (size_t)s1 * DH) + dq;
    float4 a = *o0, b = *o1;
    float4 r = make_float4(a.x + b.x, a.y + b.y, a.z + b.z, a.w + b.w);
    ((float4*)(out + (size_t)t * DH))[dq] = r;
}

// ---------------- launch -----------------------------------------------------
extern "C" void kernel_launch(void* const* d_in, const int* in_sizes, int n_in,
                              void* d_out, int out_size) {
    const float* x      = (const float*)d_in[0];   // [T, D]
    const float* gate_w = (const float*)d_in[1];   // [D, E]
    const float* fc_w   = (const float*)d_in[2];   // [E, D, F]
    const float* fc_b   = (const float*)d_in[3];   // [E, F]
    const float* proj_w = (const float*)d_in[4];   // [E, F, D]
    const float* proj_b = (const float*)d_in[5];   // [E, D]

    float* out = (float*)d_out;
    float* out_logits =
        (out_size >= NTOK * DH + NTOK * NEXP) ? (out + (size_t)NTOK * DH) : nullptr;

    init_kernel<<<1, 32>>>();
    router_kernel<<<NTOK / 8, 256>>>(x, gate_w, out_logits);
    scan_kernel<<<1, 32>>>();
    scatter_kernel<<<NTOK / 128, 128>>>();

    dim3 g1(FH / TN, NSLOT / TM, NEXP);   // (64, 128, 8) — y over max rows/expert
    gemm1_kernel<<<dim3(FH / TN, NTOK / TM, NEXP), 256>>>(x, fc_w, fc_b);
    gemm2_kernel<<<dim3(DH / TN, NTOK / TM, NEXP), 256>>>(proj_w, proj_b);

    combine_kernel<<<(NTOK * (DH / 4) + 255) / 256, 256>>>(out);
    (void)g1; (void)n_in; (void)in_sizes;
}

// round 3
// speedup vs baseline: 2.2775x; 2.2775x over previous
#include <cuda_runtime.h>
#include <cuda_bf16.h>
#include <math.h>
#include <stdint.h>

// Problem constants
#define NEXP 8
#define TOPK 2
#define DH   1024
#define FH   4096
#define NTOK 4096
#define NSLOT (NTOK * TOPK)   // 8192

// ---------------- scratch (static __device__ — no allocations) -------------
__device__ __nv_bfloat16 g_X_hi[(size_t)NTOK * DH];
__device__ __nv_bfloat16 g_X_lo[(size_t)NTOK * DH];
__device__ __nv_bfloat16 g_fcwT_hi[(size_t)NEXP * FH * DH];  // [e][n(F)][k(D)]
__device__ __nv_bfloat16 g_fcwT_lo[(size_t)NEXP * FH * DH];
__device__ __nv_bfloat16 g_prjT_hi[(size_t)NEXP * DH * FH];  // [e][n(D)][k(F)]
__device__ __nv_bfloat16 g_prjT_lo[(size_t)NEXP * DH * FH];
__device__ __nv_bfloat16 g_H_hi[(size_t)NSLOT * FH];
__device__ __nv_bfloat16 g_H_lo[(size_t)NSLOT * FH];
__device__ float g_O[(size_t)NSLOT * DH];
__device__ int   g_count[NEXP];
__device__ int   g_cursor[NEXP];
__device__ int   g_off[NEXP + 1];
__device__ int   g_eid[NSLOT];
__device__ float g_wk[NSLOT];
__device__ int   g_tok[NSLOT];
__device__ float g_wt[NSLOT];
__device__ int   g_slot[NSLOT];

// ---------------- generic-PTX helpers (no arch-specific features) ----------
__device__ __forceinline__ uint32_t smem_u32(const void* p) {
    uint32_t a;
    asm("{ .reg .u64 t; cvta.to.shared.u64 t, %1; cvt.u32.u64 %0, t; }" : "=r"(a) : "l"(p));
    return a;
}
__device__ __forceinline__ void cp16(uint32_t dst, const void* src, int srcsize) {
    asm volatile("cp.async.cg.shared.global [%0], [%1], 16, %2;"
                 :: "r"(dst), "l"(src), "r"(srcsize) : "memory");
}
#define CP_COMMIT() asm volatile("cp.async.commit_group;" ::: "memory")
#define CP_WAIT1()  asm volatile("cp.async.wait_group 1;" ::: "memory")

__device__ __forceinline__ void ldsm_x4(uint32_t* r, uint32_t addr) {
    asm volatile("ldmatrix.sync.aligned.m8n8.x4.shared.b16 {%0,%1,%2,%3}, [%4];"
                 : "=r"(r[0]), "=r"(r[1]), "=r"(r[2]), "=r"(r[3]) : "r"(addr));
}
__device__ __forceinline__ void mma16816(float* d, const uint32_t* a, const uint32_t* b) {
    asm volatile(
        "mma.sync.aligned.m16n8k16.row.col.f32.bf16.bf16.f32 "
        "{%0,%1,%2,%3}, {%4,%5,%6,%7}, {%8,%9}, {%0,%1,%2,%3};"
        : "+f"(d[0]), "+f"(d[1]), "+f"(d[2]), "+f"(d[3])
        : "r"(a[0]), "r"(a[1]), "r"(a[2]), "r"(a[3]), "r"(b[0]), "r"(b[1]));
}

__device__ __forceinline__ float gelu_new(float v) {
    const float c = 0.7978845608028654f;
    float u = c * (v + 0.044715f * v * v * v);
    return 0.5f * v * (1.0f + tanhf(u));
}
__device__ __forceinline__ uint32_t pack2(__nv_bfloat16 a, __nv_bfloat16 b) {
    return (uint32_t)__bfloat16_as_ushort(a) | ((uint32_t)__bfloat16_as_ushort(b) << 16);
}

// SMEM tile geometry: [128 rows][40 bf16] per quarter (data in cols 0..31)
#define SROW_B   80           // bytes per row (40 bf16) — conflict-free ldmatrix
#define QTILE_B  (128 * SROW_B)        // 10240
#define STAGE_B  (4 * QTILE_B)         // 40960: Ah,Al,Bh,Bl
#define SMEM_G1  (2 * STAGE_B + 512)   // + token list
#define SMEM_G2  (2 * STAGE_B)

// ---------------- routing kernels -------------------------------------------
__global__ void init_kernel() {
    int i = threadIdx.x;
    if (i < NEXP) { g_count[i] = 0; g_cursor[i] = 0; }
}

__global__ void router_kernel(const float* __restrict__ x,
                              const float* __restrict__ gate_w,
                              float* __restrict__ out_logits) {
    int warp = (blockIdx.x * blockDim.x + threadIdx.x) >> 5;
    int lane = threadIdx.x & 31;
    if (warp >= NTOK) return;
    const float* xp = x + (size_t)warp * DH;
    float acc[NEXP];
#pragma unroll
    for (int e = 0; e < NEXP; e++) acc[e] = 0.0f;
    for (int d = lane; d < DH; d += 32) {
        float xv = xp[d];
        const float* gw = gate_w + d * NEXP;
#pragma unroll
        for (int e = 0; e < NEXP; e++) acc[e] += xv * gw[e];
    }
#pragma unroll
    for (int e = 0; e < NEXP; e++)
#pragma unroll
        for (int o = 16; o > 0; o >>= 1)
            acc[e] += __shfl_xor_sync(0xffffffffu, acc[e], o);
    if (lane == 0) {
        if (out_logits)
#pragma unroll
            for (int e = 0; e < NEXP; e++) out_logits[warp * NEXP + e] = acc[e];
        int e0 = 0;
#pragma unroll
        for (int e = 1; e < NEXP; e++) if (acc[e] > acc[e0]) e0 = e;
        int e1 = (e0 == 0) ? 1 : 0;
#pragma unroll
        for (int e = 0; e < NEXP; e++) if (e != e0 && acc[e] > acc[e1]) e1 = e;
        float dlt = expf(acc[e1] - acc[e0]);
        float w0 = 1.0f / (1.0f + dlt);
        float w1 = dlt / (1.0f + dlt);
        g_eid[warp * 2 + 0] = e0; g_eid[warp * 2 + 1] = e1;
        g_wk [warp * 2 + 0] = w0; g_wk [warp * 2 + 1] = w1;
        atomicAdd(&g_count[e0], 1);
        atomicAdd(&g_count[e1], 1);
    }
}

__global__ void scan_kernel() {
    if (threadIdx.x == 0) {
        int acc = 0; g_off[0] = 0;
#pragma unroll
        for (int e = 0; e < NEXP; e++) { acc += g_count[e]; g_off[e + 1] = acc; }
    }
}

__global__ void scatter_kernel() {
    int t = blockIdx.x * blockDim.x + threadIdx.x;
    if (t >= NTOK) return;
#pragma unroll
    for (int k = 0; k < TOPK; k++) {
        int e = g_eid[t * 2 + k];
        int pos = g_off[e] + atomicAdd(&g_cursor[e], 1);
        g_tok[pos] = t;
        g_wt[pos]  = g_wk[t * 2 + k];
        g_slot[t * 2 + k] = pos;
    }
}

// ------------- x split into bf16 hi/lo ---------------------------------------
__global__ __launch_bounds__(256)
void split_x_kernel(const float* __restrict__ x) {
    int i = blockIdx.x * blockDim.x + threadIdx.x;   // over NTOK*DH/4
    if (i >= NTOK * DH / 4) return;
    float4 v = ((const float4*)x)[i];
    __nv_bfloat16 h0 = __float2bfloat16(v.x), h1 = __float2bfloat16(v.y);
    __nv_bfloat16 h2 = __float2bfloat16(v.z), h3 = __float2bfloat16(v.w);
    uint2 hv, lv;
    hv.x = pack2(h0, h1); hv.y = pack2(h2, h3);
    lv.x = pack2(__float2bfloat16(v.x - __bfloat162float(h0)),
                 __float2bfloat16(v.y - __bfloat162float(h1)));
    lv.y = pack2(__float2bfloat16(v.z - __bfloat162float(h2)),
                 __float2bfloat16(v.w - __bfloat162float(h3)));
    ((uint2*)g_X_hi)[i] = hv;
    ((uint2*)g_X_lo)[i] = lv;
}

// ------------- weight transpose + bf16 hi/lo split ---------------------------
__global__ __launch_bounds__(256)
void transpose_split_kernel(const float* __restrict__ src,
                            __nv_bfloat16* __restrict__ dh,
                            __nv_bfloat16* __restrict__ dl,
                            int K, int N) {
    __shared__ float t[32][33];
    int e = blockIdx.z;
    src += (size_t)e * K * N;
    dh  += (size_t)e * K * N;
    dl  += (size_t)e * K * N;
    int n0 = blockIdx.x * 32, k0 = blockIdx.y * 32;
    int xx = threadIdx.x, yy = threadIdx.y;  // (32, 8)
#pragma unroll
    for (int r = 0; r < 4; r++) {
        int k = yy + r * 8;
        t[k][xx] = src[(size_t)(k0 + k) * N + n0 + xx];
    }
    __syncthreads();
#pragma unroll
    for (int r = 0; r < 4; r++) {
        int n = yy + r * 8;
        float v = t[xx][n];
        __nv_bfloat16 h = __float2bfloat16(v);
        dh[(size_t)(n0 + n) * K + k0 + xx] = h;
        dl[(size_t)(n0 + n) * K + k0 + xx] = __float2bfloat16(v - __bfloat162float(h));
    }
}

// ---------------- shared warp-level GEMM core --------------------------------
// Computes per-warp 64x32 fp32 accum over one 32-wide k stage from smem.
struct WarpAcc { float a[4][4][4]; };

__device__ __forceinline__ void compute_stage(uint32_t stbase, int lane, int wm, int wn,
                                              WarpAcc& W) {
#pragma unroll
    for (int kk = 0; kk < 32; kk += 16) {
        uint32_t ah[4][4], al[4][4], bh[4][2], bl[4][2];
        // A fragments (hi & lo)
        uint32_t aoff = stbase
                      + (uint32_t)(wm + (lane & 15)) * SROW_B
                      + (uint32_t)(kk + ((lane >> 4) << 3)) * 2;
#pragma unroll
        for (int mi = 0; mi < 4; mi++) {
            ldsm_x4(ah[mi], aoff + mi * 16 * SROW_B);
            ldsm_x4(al[mi], aoff + mi * 16 * SROW_B + QTILE_B);
        }
        // B fragments: two x4 loads give 4 n-frags each for hi & lo
        int bgrp = lane >> 3;
        uint32_t boff = stbase + 2 * QTILE_B
                      + (uint32_t)(wn + (lane & 7) + ((bgrp & 2) << 2)) * SROW_B
                      + (uint32_t)(kk + ((bgrp & 1) << 3)) * 2;
#pragma unroll
        for (int p = 0; p < 2; p++) {
            uint32_t t[4];
            ldsm_x4(t, boff + p * 16 * SROW_B);
            bh[2 * p][0] = t[0]; bh[2 * p][1] = t[1];
            bh[2 * p + 1][0] = t[2]; bh[2 * p + 1][1] = t[3];
            ldsm_x4(t, boff + p * 16 * SROW_B + QTILE_B);
            bl[2 * p][0] = t[0]; bl[2 * p][1] = t[1];
            bl[2 * p + 1][0] = t[2]; bl[2 * p + 1][1] = t[3];
        }
#pragma unroll
        for (int mi = 0; mi < 4; mi++)
#pragma unroll
            for (int ni = 0; ni < 4; ni++) {
                mma16816(W.a[mi][ni], ah[mi], bh[ni]);
                mma16816(W.a[mi][ni], ah[mi], bl[ni]);
                mma16816(W.a[mi][ni], al[mi], bh[ni]);
            }
    }
}

// ---------------- GEMM1: H = gelu(x@fc_w + b), bf16 hi/lo out ---------------
__global__ __launch_bounds__(256, 1)
void gemm1_mma(const float* __restrict__ fc_b) {
    int e = blockIdx.z;
    int row0 = g_off[e];
    int rows = g_off[e + 1] - row0;
    int m0 = blockIdx.y * 128;
    if (m0 >= rows) return;
    int n0 = blockIdx.x * 128;

    extern __shared__ char smem[];
    uint32_t sb = smem_u32(smem);
    int tid = threadIdx.x, wid = tid >> 5, lane = tid & 31;

    int* s_tok = (int*)(smem + 2 * STAGE_B);
    if (tid < 128) s_tok[tid] = (m0 + tid < rows) ? g_tok[row0 + m0 + tid] : -1;
    __syncthreads();

    const __nv_bfloat16* Bh = g_fcwT_hi + (size_t)e * FH * DH + (size_t)n0 * DH;
    const __nv_bfloat16* Bl = g_fcwT_lo + (size_t)e * FH * DH + (size_t)n0 * DH;

    const int NC = DH / 32;   // 32 stages

    // stage loader lambda-ish macro
    auto load_stage = [&](int c, int buf) {
        uint32_t stb = sb + buf * STAGE_B;
        int kt = c * 32;
#pragma unroll
        for (int part = 0; part < 8; part++) {
            int which = part >> 1;                      // 0 Ah 1 Al 2 Bh 3 Bl
            int j = ((part & 1) << 8) + tid;            // 0..511
            int row = j >> 2, ch = j & 3;
            uint32_t dst = stb + which * QTILE_B + row * SROW_B + ch * 16;
            if (which < 2) {
                int t = s_tok[row];
                const __nv_bfloat16* base = (which == 0) ? g_X_hi : g_X_lo;
                const void* src = base + (size_t)(t < 0 ? 0 : t) * DH + kt + ch * 8;
                cp16(dst, src, t < 0 ? 0 : 16);
            } else {
                const __nv_bfloat16* base = (which == 2) ? Bh : Bl;
                const void* src = base + (size_t)row * DH + kt + ch * 8;
                cp16(dst, src, 16);
            }
        }
    };

    WarpAcc W;
#pragma unroll
    for (int mi = 0; mi < 4; mi++)
#pragma unroll
        for (int ni = 0; ni < 4; ni++)
#pragma unroll
            for (int r = 0; r < 4; r++) W.a[mi][ni][r] = 0.0f;

    int wm = (wid & 1) * 64, wn = (wid >> 1) * 32;

    load_stage(0, 0); CP_COMMIT();
    for (int c = 0; c < NC; c++) {
        if (c + 1 < NC) load_stage(c + 1, (c + 1) & 1);
        CP_COMMIT();
        CP_WAIT1();
        __syncthreads();
        compute_stage(sb + (c & 1) * STAGE_B, lane, wm, wn, W);
        __syncthreads();
    }

    // epilogue: bias + gelu + split-store
    const float* bias = fc_b + (size_t)e * FH;
#pragma unroll
    for (int mi = 0; mi < 4; mi++) {
#pragma unroll
        for (int rh = 0; rh < 2; rh++) {
            int m = wm + mi * 16 + (lane >> 2) + rh * 8;
            if (m0 + m >= rows) continue;
            size_t slot = (size_t)row0 + m0 + m;
#pragma unroll
            for (int ni = 0; ni < 4; ni++) {
                int n = n0 + wn + ni * 8 + 2 * (lane & 3);
                float2 bb = *(const float2*)(bias + n);
                float v0 = gelu_new(W.a[mi][ni][2 * rh + 0] + bb.x);
                float v1 = gelu_new(W.a[mi][ni][2 * rh + 1] + bb.y);
                __nv_bfloat16 h0 = __float2bfloat16(v0), h1 = __float2bfloat16(v1);
                __nv_bfloat16 l0 = __float2bfloat16(v0 - __bfloat162float(h0));
                __nv_bfloat16 l1 = __float2bfloat16(v1 - __bfloat162float(h1));
                *(uint32_t*)(g_H_hi + slot * FH + n) = pack2(h0, h1);
                *(uint32_t*)(g_H_lo + slot * FH + n) = pack2(l0, l1);
            }
        }
    }
}

// ---------------- GEMM2: O = wt * (H@proj_w + b) -----------------------------
__global__ __launch_bounds__(256, 1)
void gemm2_mma(const float* __restrict__ proj_b) {
    int e = blockIdx.z;
    int row0 = g_off[e];
    int rows = g_off[e + 1] - row0;
    int m0 = blockIdx.y * 128;
    if (m0 >= rows) return;
    int n0 = blockIdx.x * 128;

    extern __shared__ char smem[];
    uint32_t sb = smem_u32(smem);
    int tid = threadIdx.x, wid = tid >> 5, lane = tid & 31;

    const __nv_bfloat16* Bh = g_prjT_hi + (size_t)e * DH * FH + (size_t)n0 * FH;
    const __nv_bfloat16* Bl = g_prjT_lo + (size_t)e * DH * FH + (size_t)n0 * FH;

    const int NC = FH / 32;   // 128 stages

    auto load_stage = [&](int c, int buf) {
        uint32_t stb = sb + buf * STAGE_B;
        int kt = c * 32;
#pragma unroll
        for (int part = 0; part < 8; part++) {
            int which = part >> 1;
            int j = ((part & 1) << 8) + tid;
            int row = j >> 2, ch = j & 3;
            uint32_t dst = stb + which * QTILE_B + row * SROW_B + ch * 16;
            if (which < 2) {
                bool ok = (m0 + row) < rows;
                size_t slot = (size_t)row0 + m0 + (ok ? row : 0);
                const __nv_bfloat16* base = (which == 0) ? g_H_hi : g_H_lo;
                const void* src = base + slot * FH + kt + ch * 8;
                cp16(dst, src, ok ? 16 : 0);
            } else {
                const __nv_bfloat16* base = (which == 2) ? Bh : Bl;
                const void* src = base + (size_t)row * FH + kt + ch * 8;
                cp16(dst, src, 16);
            }
        }
    };

    WarpAcc W;
#pragma unroll
    for (int mi = 0; mi < 4; mi++)
#pragma unroll
        for (int ni = 0; ni < 4; ni++)
#pragma unroll
            for (int r = 0; r < 4; r++) W.a[mi][ni][r] = 0.0f;

    int wm = (wid & 1) * 64, wn = (wid >> 1) * 32;

    load_stage(0, 0); CP_COMMIT();
    for (int c = 0; c < NC; c++) {
        if (c + 1 < NC) load_stage(c + 1, (c + 1) & 1);
        CP_COMMIT();
        CP_WAIT1();
        __syncthreads();
        compute_stage(sb + (c & 1) * STAGE_B, lane, wm, wn, W);
        __syncthreads();
    }

    const float* bias = proj_b + (size_t)e * DH;
#pragma unroll
    for (int mi = 0; mi < 4; mi++) {
#pragma unroll
        for (int rh = 0; rh < 2; rh++) {
            int m = wm + mi * 16 + (lane >> 2) + rh * 8;
            if (m0 + m >= rows) continue;
            size_t slot = (size_t)row0 + m0 + m;
            float w = g_wt[slot];
#pragma unroll
            for (int ni = 0; ni < 4; ni++) {
                int n = n0 + wn + ni * 8 + 2 * (lane & 3);
                float2 bb = *(const float2*)(bias + n);
                float v0 = w * (W.a[mi][ni][2 * rh + 0] + bb.x);
                float v1 = w * (W.a[mi][ni][2 * rh + 1] + bb.y);
                *(float2*)(g_O + slot * DH + n) = make_float2(v0, v1);
            }
        }
    }
}

// ---------------- combine ----------------------------------------------------
__global__ void combine_kernel(float* __restrict__ out) {
    int idx = blockIdx.x * blockDim.x + threadIdx.x;
    const int DQ = DH / 4;
    if (idx >= NTOK * DQ) return;
    int t = idx / DQ;
    int dq = idx - t * DQ;
    int s0 = g_slot[t * 2 + 0];
    int s1 = g_slot[t * 2 + 1];
    const float4* o0 = (const float4*)(g_O + (size_t)s0 * DH) + dq;
    const float4* o1 = (const float4*)(g_O + (size_t)s1 * DH) + dq;
    float4 a = *o0, b = *o1;
    ((float4*)(out + (size_t)t * DH))[dq] =
        make_float4(a.x + b.x, a.y + b.y, a.z + b.z, a.w + b.w);
}

// ---------------- launch -----------------------------------------------------
extern "C" void kernel_launch(void* const* d_in, const int* in_sizes, int n_in,
                              void* d_out, int out_size) {
    const float* x      = (const float*)d_in[0];
    const float* gate_w = (const float*)d_in[1];
    const float* fc_w   = (const float*)d_in[2];
    const float* fc_b   = (const float*)d_in[3];
    const float* proj_w = (const float*)d_in[4];
    const float* proj_b = (const float*)d_in[5];

    float* out = (float*)d_out;
    float* out_logits =
        (out_size >= NTOK * DH + NTOK * NEXP) ? (out + (size_t)NTOK * DH) : nullptr;

    cudaFuncSetAttribute(gemm1_mma, cudaFuncAttributeMaxDynamicSharedMemorySize, SMEM_G1);
    cudaFuncSetAttribute(gemm2_mma, cudaFuncAttributeMaxDynamicSharedMemorySize, SMEM_G2);

    init_kernel<<<1, 32>>>();
    router_kernel<<<NTOK / 8, 256>>>(x, gate_w, out_logits);
    scan_kernel<<<1, 32>>>();
    scatter_kernel<<<NTOK / 128, 128>>>();
    split_x_kernel<<<(NTOK * DH / 4 + 255) / 256, 256>>>(x);

    {
        __nv_bfloat16 *fh, *fl, *ph, *pl;
        cudaGetSymbolAddress((void**)&fh, g_fcwT_hi);
        cudaGetSymbolAddress((void**)&fl, g_fcwT_lo);
        cudaGetSymbolAddress((void**)&ph, g_prjT_hi);
        cudaGetSymbolAddress((void**)&pl, g_prjT_lo);
        transpose_split_kernel<<<dim3(FH / 32, DH / 32, NEXP), dim3(32, 8)>>>(fc_w, fh, fl, DH, FH);
        transpose_split_kernel<<<dim3(DH / 32, FH / 32, NEXP), dim3(32, 8)>>>(proj_w, ph, pl, FH, DH);
    }

    gemm1_mma<<<dim3(FH / 128, NTOK / 128, NEXP), 256, SMEM_G1>>>(fc_b);
    gemm2_mma<<<dim3(DH / 128, NTOK / 128, NEXP), 256, SMEM_G2>>>(proj_b);

    combine_kernel<<<(NTOK * (DH / 4) + 255) / 256, 256>>>(out);
    (void)n_in; (void)in_sizes;
}

// round 4
// speedup vs baseline: 2.4999x; 1.0977x over previous
#include <cuda_runtime.h>
#include <cuda_bf16.h>
#include <math.h>
#include <stdint.h>

// Problem constants
#define NEXP 8
#define TOPK 2
#define DH   1024
#define FH   4096
#define NTOK 4096
#define NSLOT (NTOK * TOPK)   // 8192

// ---------------- scratch (static __device__ — no allocations) -------------
__device__ __nv_bfloat16 g_X_hi[(size_t)NTOK * DH];
__device__ __nv_bfloat16 g_X_lo[(size_t)NTOK * DH];
__device__ __nv_bfloat16 g_fcwT_hi[(size_t)NEXP * FH * DH];  // [e][n(F)][k(D)]
__device__ __nv_bfloat16 g_fcwT_lo[(size_t)NEXP * FH * DH];
__device__ __nv_bfloat16 g_prjT_hi[(size_t)NEXP * DH * FH];  // [e][n(D)][k(F)]
__device__ __nv_bfloat16 g_prjT_lo[(size_t)NEXP * DH * FH];
__device__ __nv_bfloat16 g_H_hi[(size_t)NSLOT * FH];
__device__ __nv_bfloat16 g_H_lo[(size_t)NSLOT * FH];
__device__ float g_O[(size_t)NSLOT * DH];
__device__ int   g_count[NEXP];
__device__ int   g_cursor[NEXP];
__device__ int   g_off[NEXP + 1];
__device__ int   g_eid[NSLOT];
__device__ float g_wk[NSLOT];
__device__ int   g_tok[NSLOT];
__device__ float g_wt[NSLOT];
__device__ int   g_slot[NSLOT];

// ---------------- generic-PTX helpers ---------------------------------------
__device__ __forceinline__ uint32_t smem_u32(const void* p) {
    uint32_t a;
    asm("{ .reg .u64 t; cvta.to.shared.u64 t, %1; cvt.u32.u64 %0, t; }" : "=r"(a) : "l"(p));
    return a;
}
__device__ __forceinline__ void cp16(uint32_t dst, const void* src, int srcsize) {
    asm volatile("cp.async.cg.shared.global [%0], [%1], 16, %2;"
                 :: "r"(dst), "l"(src), "r"(srcsize) : "memory");
}
#define CP_COMMIT() asm volatile("cp.async.commit_group;" ::: "memory")
#define CP_WAIT1()  asm volatile("cp.async.wait_group 1;" ::: "memory")

__device__ __forceinline__ void ldsm_x4(uint32_t* r, uint32_t addr) {
    asm volatile("ldmatrix.sync.aligned.m8n8.x4.shared.b16 {%0,%1,%2,%3}, [%4];"
                 : "=r"(r[0]), "=r"(r[1]), "=r"(r[2]), "=r"(r[3]) : "r"(addr));
}
__device__ __forceinline__ void mma16816(float* d, const uint32_t* a, uint32_t b0, uint32_t b1) {
    asm volatile(
        "mma.sync.aligned.m16n8k16.row.col.f32.bf16.bf16.f32 "
        "{%0,%1,%2,%3}, {%4,%5,%6,%7}, {%8,%9}, {%0,%1,%2,%3};"
        : "+f"(d[0]), "+f"(d[1]), "+f"(d[2]), "+f"(d[3])
        : "r"(a[0]), "r"(a[1]), "r"(a[2]), "r"(a[3]), "r"(b0), "r"(b1));
}

__device__ __forceinline__ float gelu_new(float v) {
    const float c = 0.7978845608028654f;
    float u = c * (v + 0.044715f * v * v * v);
    return 0.5f * v * (1.0f + tanhf(u));
}
__device__ __forceinline__ uint32_t pack2(__nv_bfloat16 a, __nv_bfloat16 b) {
    return (uint32_t)__bfloat16_as_ushort(a) | ((uint32_t)__bfloat16_as_ushort(b) << 16);
}

// SMEM tile geometry: row = 80 B (32 bf16 data + pad), conflict-free ldmatrix
#define SROW_B   80
#define OFF_AH   0
#define OFF_AL   10240              // 128 rows * 80
#define OFF_BH   20480
#define OFF_BL   40960              // Bh is 256 rows * 80 = 20480
#define STAGE_B  61440
#define NSTAGE   3
#define SMEM_G1  (NSTAGE * STAGE_B + 512)
#define SMEM_G2  (NSTAGE * STAGE_B)

// ---------------- routing kernels -------------------------------------------
__global__ void init_kernel() {
    int i = threadIdx.x;
    if (i < NEXP) { g_count[i] = 0; g_cursor[i] = 0; }
}

__global__ void router_kernel(const float* __restrict__ x,
                              const float* __restrict__ gate_w,
                              float* __restrict__ out_logits) {
    int warp = (blockIdx.x * blockDim.x + threadIdx.x) >> 5;
    int lane = threadIdx.x & 31;
    if (warp >= NTOK) return;
    const float* xp = x + (size_t)warp * DH;
    float acc[NEXP];
#pragma unroll
    for (int e = 0; e < NEXP; e++) acc[e] = 0.0f;
    for (int d = lane; d < DH; d += 32) {
        float xv = xp[d];
        const float* gw = gate_w + d * NEXP;
#pragma unroll
        for (int e = 0; e < NEXP; e++) acc[e] += xv * gw[e];
    }
#pragma unroll
    for (int e = 0; e < NEXP; e++)
#pragma unroll
        for (int o = 16; o > 0; o >>= 1)
            acc[e] += __shfl_xor_sync(0xffffffffu, acc[e], o);
    if (lane == 0) {
        if (out_logits)
#pragma unroll
            for (int e = 0; e < NEXP; e++) out_logits[warp * NEXP + e] = acc[e];
        int e0 = 0;
#pragma unroll
        for (int e = 1; e < NEXP; e++) if (acc[e] > acc[e0]) e0 = e;
        int e1 = (e0 == 0) ? 1 : 0;
#pragma unroll
        for (int e = 0; e < NEXP; e++) if (e != e0 && acc[e] > acc[e1]) e1 = e;
        float dlt = expf(acc[e1] - acc[e0]);
        float w0 = 1.0f / (1.0f + dlt);
        float w1 = dlt / (1.0f + dlt);
        g_eid[warp * 2 + 0] = e0; g_eid[warp * 2 + 1] = e1;
        g_wk [warp * 2 + 0] = w0; g_wk [warp * 2 + 1] = w1;
        atomicAdd(&g_count[e0], 1);
        atomicAdd(&g_count[e1], 1);
    }
}

__global__ void scan_kernel() {
    if (threadIdx.x == 0) {
        int acc = 0; g_off[0] = 0;
#pragma unroll
        for (int e = 0; e < NEXP; e++) { acc += g_count[e]; g_off[e + 1] = acc; }
    }
}

__global__ void scatter_kernel() {
    int t = blockIdx.x * blockDim.x + threadIdx.x;
    if (t >= NTOK) return;
#pragma unroll
    for (int k = 0; k < TOPK; k++) {
        int e = g_eid[t * 2 + k];
        int pos = g_off[e] + atomicAdd(&g_cursor[e], 1);
        g_tok[pos] = t;
        g_wt[pos]  = g_wk[t * 2 + k];
        g_slot[t * 2 + k] = pos;
    }
}

// ------------- x split into bf16 hi/lo ---------------------------------------
__global__ __launch_bounds__(256)
void split_x_kernel(const float* __restrict__ x) {
    int i = blockIdx.x * blockDim.x + threadIdx.x;
    if (i >= NTOK * DH / 4) return;
    float4 v = ((const float4*)x)[i];
    __nv_bfloat16 h0 = __float2bfloat16(v.x), h1 = __float2bfloat16(v.y);
    __nv_bfloat16 h2 = __float2bfloat16(v.z), h3 = __float2bfloat16(v.w);
    uint2 hv, lv;
    hv.x = pack2(h0, h1); hv.y = pack2(h2, h3);
    lv.x = pack2(__float2bfloat16(v.x - __bfloat162float(h0)),
                 __float2bfloat16(v.y - __bfloat162float(h1)));
    lv.y = pack2(__float2bfloat16(v.z - __bfloat162float(h2)),
                 __float2bfloat16(v.w - __bfloat162float(h3)));
    ((uint2*)g_X_hi)[i] = hv;
    ((uint2*)g_X_lo)[i] = lv;
}

// ------------- weight transpose + bf16 hi/lo split ---------------------------
__global__ __launch_bounds__(256)
void transpose_split_kernel(const float* __restrict__ src,
                            __nv_bfloat16* __restrict__ dh,
                            __nv_bfloat16* __restrict__ dl,
                            int K, int N) {
    __shared__ float t[32][33];
    int e = blockIdx.z;
    src += (size_t)e * K * N;
    dh  += (size_t)e * K * N;
    dl  += (size_t)e * K * N;
    int n0 = blockIdx.x * 32, k0 = blockIdx.y * 32;
    int xx = threadIdx.x, yy = threadIdx.y;  // (32, 8)
#pragma unroll
    for (int r = 0; r < 4; r++) {
        int k = yy + r * 8;
        t[k][xx] = src[(size_t)(k0 + k) * N + n0 + xx];
    }
    __syncthreads();
#pragma unroll
    for (int r = 0; r < 4; r++) {
        int n = yy + r * 8;
        float v = t[xx][n];
        __nv_bfloat16 h = __float2bfloat16(v);
        dh[(size_t)(n0 + n) * K + k0 + xx] = h;
        dl[(size_t)(n0 + n) * K + k0 + xx] = __float2bfloat16(v - __bfloat162float(h));
    }
}

// ---------------- warp-level 64x64 3-pass compute over one 32-wide stage ----
struct WarpAcc { float a[4][8][4]; };   // [mi][ni][frag]

__device__ __forceinline__ void compute_stage(uint32_t stb, int lane, int wm, int wn,
                                              WarpAcc& W) {
#pragma unroll
    for (int kk = 0; kk < 32; kk += 16) {
        uint32_t ah[4][4], al[4][4];
        uint32_t aoff = stb + OFF_AH
                      + (uint32_t)(wm + (lane & 15)) * SROW_B
                      + (uint32_t)(kk + ((lane >> 4) << 3)) * 2;
#pragma unroll
        for (int mi = 0; mi < 4; mi++) {
            ldsm_x4(ah[mi], aoff + mi * 16 * SROW_B);
            ldsm_x4(al[mi], aoff + mi * 16 * SROW_B + (OFF_AL - OFF_AH));
        }
        int bgrp = lane >> 3;
        uint32_t boff = stb + OFF_BH
                      + (uint32_t)(wn + (lane & 7) + ((bgrp & 2) << 2)) * SROW_B
                      + (uint32_t)(kk + ((bgrp & 1) << 3)) * 2;
#pragma unroll
        for (int p = 0; p < 4; p++) {           // ni pair (2p, 2p+1)
            uint32_t th[4], tl[4];
            ldsm_x4(th, boff + p * 16 * SROW_B);
            ldsm_x4(tl, boff + p * 16 * SROW_B + (OFF_BL - OFF_BH));
#pragma unroll
            for (int mi = 0; mi < 4; mi++) {
                mma16816(W.a[mi][2 * p],     ah[mi], th[0], th[1]);
                mma16816(W.a[mi][2 * p],     ah[mi], tl[0], tl[1]);
                mma16816(W.a[mi][2 * p],     al[mi], th[0], th[1]);
                mma16816(W.a[mi][2 * p + 1], ah[mi], th[2], th[3]);
                mma16816(W.a[mi][2 * p + 1], ah[mi], tl[2], tl[3]);
                mma16816(W.a[mi][2 * p + 1], al[mi], th[2], th[3]);
            }
        }
    }
}

// ---------------- GEMM1: H = gelu(x@fc_w + b), 128x256 tile ------------------
__global__ __launch_bounds__(256, 1)
void gemm1_mma(const float* __restrict__ fc_b) {
    int e = blockIdx.z;
    int row0 = g_off[e];
    int rows = g_off[e + 1] - row0;
    int m0 = blockIdx.y * 128;
    if (m0 >= rows) return;
    int n0 = blockIdx.x * 256;

    extern __shared__ char smem[];
    uint32_t sb = smem_u32(smem);
    int tid = threadIdx.x, wid = tid >> 5, lane = tid & 31;

    int* s_tok = (int*)(smem + NSTAGE * STAGE_B);
    if (tid < 128) s_tok[tid] = (m0 + tid < rows) ? g_tok[row0 + m0 + tid] : -1;
    __syncthreads();

    const __nv_bfloat16* Bh = g_fcwT_hi + (size_t)e * FH * DH + (size_t)n0 * DH;
    const __nv_bfloat16* Bl = g_fcwT_lo + (size_t)e * FH * DH + (size_t)n0 * DH;

    const int NC = DH / 32;   // 32 stages

    auto load_stage = [&](int c) {
        uint32_t stb = sb + (c % NSTAGE) * STAGE_B;
        int kt = c * 32;
        // A: 128 rows hi + 128 rows lo
#pragma unroll
        for (int i = 0; i < 4; i++) {
            int u = tid + (i & 1) * 256;
            int row = u >> 2, ch = u & 3;
            int which = i >> 1;   // 0 hi, 1 lo
            uint32_t dst = stb + (which ? OFF_AL : OFF_AH) + row * SROW_B + ch * 16;
            int t = s_tok[row];
            const __nv_bfloat16* base = which ? g_X_lo : g_X_hi;
            const void* src = base + (size_t)(t < 0 ? 0 : t) * DH + kt + ch * 8;
            cp16(dst, src, t < 0 ? 0 : 16);
        }
        // B: 256 rows hi + 256 rows lo
#pragma unroll
        for (int i = 0; i < 8; i++) {
            int u = tid + (i & 3) * 256;
            int row = u >> 2, ch = u & 3;
            int which = i >> 2;
            uint32_t dst = stb + (which ? OFF_BL : OFF_BH) + row * SROW_B + ch * 16;
            const __nv_bfloat16* base = which ? Bl : Bh;
            const void* src = base + (size_t)row * DH + kt + ch * 8;
            cp16(dst, src, 16);
        }
    };

    WarpAcc W;
#pragma unroll
    for (int mi = 0; mi < 4; mi++)
#pragma unroll
        for (int ni = 0; ni < 8; ni++)
#pragma unroll
            for (int r = 0; r < 4; r++) W.a[mi][ni][r] = 0.0f;

    int wm = (wid & 1) * 64, wn = (wid >> 1) * 64;

    load_stage(0); CP_COMMIT();
    load_stage(1); CP_COMMIT();
    for (int c = 0; c < NC; c++) {
        CP_WAIT1();
        __syncthreads();
        if (c + 2 < NC) load_stage(c + 2);
        CP_COMMIT();
        compute_stage(sb + (c % NSTAGE) * STAGE_B, lane, wm, wn, W);
    }

    const float* bias = fc_b + (size_t)e * FH;
#pragma unroll
    for (int mi = 0; mi < 4; mi++) {
#pragma unroll
        for (int rh = 0; rh < 2; rh++) {
            int m = wm + mi * 16 + (lane >> 2) + rh * 8;
            if (m0 + m >= rows) continue;
            size_t slot = (size_t)row0 + m0 + m;
#pragma unroll
            for (int ni = 0; ni < 8; ni++) {
                int n = n0 + wn + ni * 8 + 2 * (lane & 3);
                float2 bb = *(const float2*)(bias + n);
                float v0 = gelu_new(W.a[mi][ni][2 * rh + 0] + bb.x);
                float v1 = gelu_new(W.a[mi][ni][2 * rh + 1] + bb.y);
                __nv_bfloat16 h0 = __float2bfloat16(v0), h1 = __float2bfloat16(v1);
                __nv_bfloat16 l0 = __float2bfloat16(v0 - __bfloat162float(h0));
                __nv_bfloat16 l1 = __float2bfloat16(v1 - __bfloat162float(h1));
                *(uint32_t*)(g_H_hi + slot * FH + n) = pack2(h0, h1);
                *(uint32_t*)(g_H_lo + slot * FH + n) = pack2(l0, l1);
            }
        }
    }
}

// ---------------- GEMM2: O = wt * (H@proj_w + b), 128x256 tile ---------------
__global__ __launch_bounds__(256, 1)
void gemm2_mma(const float* __restrict__ proj_b) {
    int e = blockIdx.z;
    int row0 = g_off[e];
    int rows = g_off[e + 1] - row0;
    int m0 = blockIdx.y * 128;
    if (m0 >= rows) return;
    int n0 = blockIdx.x * 256;

    extern __shared__ char smem[];
    uint32_t sb = smem_u32(smem);
    int tid = threadIdx.x, wid = tid >> 5, lane = tid & 31;

    const __nv_bfloat16* Bh = g_prjT_hi + (size_t)e * DH * FH + (size_t)n0 * FH;
    const __nv_bfloat16* Bl = g_prjT_lo + (size_t)e * DH * FH + (size_t)n0 * FH;

    const int NC = FH / 32;   // 128 stages

    auto load_stage = [&](int c) {
        uint32_t stb = sb + (c % NSTAGE) * STAGE_B;
        int kt = c * 32;
#pragma unroll
        for (int i = 0; i < 4; i++) {
            int u = tid + (i & 1) * 256;
            int row = u >> 2, ch = u & 3;
            int which = i >> 1;
            uint32_t dst = stb + (which ? OFF_AL : OFF_AH) + row * SROW_B + ch * 16;
            bool ok = (m0 + row) < rows;
            size_t slot = (size_t)row0 + m0 + (ok ? row : 0);
            const __nv_bfloat16* base = which ? g_H_lo : g_H_hi;
            const void* src = base + slot * FH + kt + ch * 8;
            cp16(dst, src, ok ? 16 : 0);
        }
#pragma unroll
        for (int i = 0; i < 8; i++) {
            int u = tid + (i & 3) * 256;
            int row = u >> 2, ch = u & 3;
            int which = i >> 2;
            uint32_t dst = stb + (which ? OFF_BL : OFF_BH) + row * SROW_B + ch * 16;
            const __nv_bfloat16* base = which ? Bl : Bh;
            const void* src = base + (size_t)row * FH + kt + ch * 8;
            cp16(dst, src, 16);
        }
    };

    WarpAcc W;
#pragma unroll
    for (int mi = 0; mi < 4; mi++)
#pragma unroll
        for (int ni = 0; ni < 8; ni++)
#pragma unroll
            for (int r = 0; r < 4; r++) W.a[mi][ni][r] = 0.0f;

    int wm = (wid & 1) * 64, wn = (wid >> 1) * 64;

    load_stage(0); CP_COMMIT();
    load_stage(1); CP_COMMIT();
    for (int c = 0; c < NC; c++) {
        CP_WAIT1();
        __syncthreads();
        if (c + 2 < NC) load_stage(c + 2);
        CP_COMMIT();
        compute_stage(sb + (c % NSTAGE) * STAGE_B, lane, wm, wn, W);
    }

    const float* bias = proj_b + (size_t)e * DH;
#pragma unroll
    for (int mi = 0; mi < 4; mi++) {
#pragma unroll
        for (int rh = 0; rh < 2; rh++) {
            int m = wm + mi * 16 + (lane >> 2) + rh * 8;
            if (m0 + m >= rows) continue;
            size_t slot = (size_t)row0 + m0 + m;
            float w = g_wt[slot];
#pragma unroll
            for (int ni = 0; ni < 8; ni++) {
                int n = n0 + wn + ni * 8 + 2 * (lane & 3);
                float2 bb = *(const float2*)(bias + n);
                float v0 = w * (W.a[mi][ni][2 * rh + 0] + bb.x);
                float v1 = w * (W.a[mi][ni][2 * rh + 1] + bb.y);
                *(float2*)(g_O + slot * DH + n) = make_float2(v0, v1);
            }
        }
    }
}

// ---------------- combine ----------------------------------------------------
__global__ void combine_kernel(float* __restrict__ out) {
    int idx = blockIdx.x * blockDim.x + threadIdx.x;
    const int DQ = DH / 4;
    if (idx >= NTOK * DQ) return;
    int t = idx / DQ;
    int dq = idx - t * DQ;
    int s0 = g_slot[t * 2 + 0];
    int s1 = g_slot[t * 2 + 1];
    const float4* o0 = (const float4*)(g_O + (size_t)s0 * DH) + dq;
    const float4* o1 = (const float4*)(g_O + (size_t)s1 * DH) + dq;
    float4 a = *o0, b = *o1;
    ((float4*)(out + (size_t)t * DH))[dq] =
        make_float4(a.x + b.x, a.y + b.y, a.z + b.z, a.w + b.w);
}

// ---------------- launch -----------------------------------------------------
extern "C" void kernel_launch(void* const* d_in, const int* in_sizes, int n_in,
                              void* d_out, int out_size) {
    const float* x      = (const float*)d_in[0];
    const float* gate_w = (const float*)d_in[1];
    const float* fc_w   = (const float*)d_in[2];
    const float* fc_b   = (const float*)d_in[3];
    const float* proj_w = (const float*)d_in[4];
    const float* proj_b = (const float*)d_in[5];

    float* out = (float*)d_out;
    float* out_logits =
        (out_size >= NTOK * DH + NTOK * NEXP) ? (out + (size_t)NTOK * DH) : nullptr;

    cudaFuncSetAttribute(gemm1_mma, cudaFuncAttributeMaxDynamicSharedMemorySize, SMEM_G1);
    cudaFuncSetAttribute(gemm2_mma, cudaFuncAttributeMaxDynamicSharedMemorySize, SMEM_G2);

    init_kernel<<<1, 32>>>();
    router_kernel<<<NTOK / 8, 256>>>(x, gate_w, out_logits);
    scan_kernel<<<1, 32>>>();
    scatter_kernel<<<NTOK / 128, 128>>>();
    split_x_kernel<<<(NTOK * DH / 4 + 255) / 256, 256>>>(x);

    {
        __nv_bfloat16 *fh, *fl, *ph, *pl;
        cudaGetSymbolAddress((void**)&fh, g_fcwT_hi);
        cudaGetSymbolAddress((void**)&fl, g_fcwT_lo);
        cudaGetSymbolAddress((void**)&ph, g_prjT_hi);
        cudaGetSymbolAddress((void**)&pl, g_prjT_lo);
        transpose_split_kernel<<<dim3(FH / 32, DH / 32, NEXP), dim3(32, 8)>>>(fc_w, fh, fl, DH, FH);
        transpose_split_kernel<<<dim3(DH / 32, FH / 32, NEXP), dim3(32, 8)>>>(proj_w, ph, pl, FH, DH);
    }

    gemm1_mma<<<dim3(FH / 256, NTOK / 128, NEXP), 256, SMEM_G1>>>(fc_b);
    gemm2_mma<<<dim3(DH / 256, NTOK / 128, NEXP), 256, SMEM_G2>>>(proj_b);

    combine_kernel<<<(NTOK * (DH / 4) + 255) / 256, 256>>>(out);
    (void)n_in; (void)in_sizes;
}